// round 14
// baseline (speedup 1.0000x reference)
#include <cuda_runtime.h>
#include <cuda_bf16.h>

// p1, p2: [B=2, C=32, D=96, H=96, W=96] fp32
// pool to S=8 (cells 12^3), L = 512 tokens, C = 32 channels.
// loss = (1/(L^2 B)) * sum_b [ ||Ga||F^2 + ||Gb||F^2 - 2||Gx||F^2 ]
// with G = (normalized tokens)^T (normalized tokens). Normalization folded
// into the Gram inner loop as per-token weights w_l = 1/n_l (per side).
//
// Single launch, 8224 blocks:
//   bid <  8192 : pool block (b,pd,ph,c,t packed so each chunk's 256
//                 contributors are CONTIGUOUS in bid order), ends with a
//                 release-fence + ticket on its chunk counter.
//   bid >= 8192 : 32 dedicated sim blocks (dispatched last). Each spins on
//                 its chunk counter, computes that chunk's partial Grams,
//                 atomically accumulates; the last done-ticket block
//                 finalizes and resets state for graph replay.

#define BATCH 2
#define CH    32
#define DIM   96
#define LTOK  512
#define BLK   12
#define EPS   1e-8f
#define LSTR  33
#define NCHUNK 32
#define CONTRIB 256
#define POOL_BLOCKS 8192

// pooled tokens token-major: [tensor(2)][b(2)][l(512)][c(32)]
__device__ float g_pooled[2 * BATCH * LTOK * CH];
// Grams: [b(2)][g(3: aa, bb, ab)][i(32)][j(32)] (zero-init; finalizer re-zeroes)
__device__ float g_gram[BATCH * 3 * CH * CH];
__device__ unsigned int g_chunk_cnt[NCHUNK];   // reset by consumer
__device__ unsigned int g_done;                // reset by finalizer

__global__ __launch_bounds__(96, 20)
void fused_kernel(const float* __restrict__ p1,
                  const float* __restrict__ p2,
                  float* __restrict__ out)
{
    const int bid = blockIdx.x;
    const int tid = threadIdx.x;

    __shared__ float sh[2 * CH * LSTR];   // sim: raw tokens [t][c][l] (8.4 KB)
    __shared__ float shinv[2 * 32];       // sim: per-token 1/norm
    __shared__ float shred[96];           // pool: partial sums
    __shared__ float wsum[3];
    __shared__ unsigned int s_flag;

    if (bid < POOL_BLOCKS) {
        // ---------------- pool path (identical math to 65.3us kernel) -----
        const int t  = bid & 1;
        const int c  = (bid >> 1) & 31;
        const int ph = (bid >> 6) & 7;
        const int pd = (bid >> 9) & 7;
        const int b  = (bid >> 12) & 1;

        const float* __restrict__ in = t ? p2 : p1;
        const int f4 = tid % 24;    // w = 4*f4
        const int rs = tid / 24;    // d chunk [3rs, 3rs+3)

        const float* __restrict__ base =
            in + ((size_t)(b * CH + c)) * (DIM * DIM * DIM)
               + (size_t)(pd * BLK + 3 * rs) * (DIM * DIM)
               + (size_t)ph * BLK * DIM
               + f4 * 4;

        float acc = 0.0f;
        #pragma unroll
        for (int d2 = 0; d2 < 3; ++d2) {
            #pragma unroll
            for (int h = 0; h < 12; ++h) {
                const float4 v = __ldcs(reinterpret_cast<const float4*>(
                    base + d2 * (DIM * DIM) + h * DIM));
                acc += (v.x + v.y) + (v.z + v.w);
            }
        }

        shred[tid] = acc;
        __syncthreads();

        if (tid < 8) {
            float s = 0.0f;
            #pragma unroll
            for (int r2 = 0; r2 < 4; ++r2)
                #pragma unroll
                for (int j = 0; j < 3; ++j)
                    s += shred[r2 * 24 + tid * 3 + j];
            const int l = pd * 64 + ph * 8 + tid;
            g_pooled[(((size_t)t * BATCH + b) * LTOK + l) * CH + c] =
                s * (1.0f / (BLK * BLK * BLK));
            __threadfence();   // release pooled write
        }
        __syncthreads();
        if (tid == 0)
            atomicAdd(&g_chunk_cnt[b * 16 + pd * 2 + (ph >> 2)], 1u);
        return;
    }

    // ---------------- sim path: one block per 32-token chunk --------------
    const int sid = bid - POOL_BLOCKS;      // == cid, 0..31
    const int b   = sid >> 4;
    const int l0  = (sid & 15) * 32;

    if (tid == 0) {
        while (atomicAdd(&g_chunk_cnt[sid], 0u) < CONTRIB)
            __nanosleep(128);
        atomicExch(&g_chunk_cnt[sid], 0u);   // reset for next replay
        __threadfence();                      // acquire contributors' writes
    }
    __syncthreads();

    // load raw tokens (channel-major, stride 33) + per-token inverse norms
    if (tid < 64) {
        const int tt = tid >> 5;             // tensor
        const int l  = tid & 31;
        const float* __restrict__ src =
            g_pooled + (((size_t)tt * BATCH + b) * LTOK + l0 + l) * CH;
        float s = 0.0f;
        #pragma unroll
        for (int k = 0; k < 8; ++k) {
            const float4 v = __ldcg(reinterpret_cast<const float4*>(src + 4 * k));
            s += v.x * v.x + v.y * v.y + v.z * v.z + v.w * v.w;
            float* d = sh + tt * CH * LSTR + (4 * k) * LSTR + l;
            d[0 * LSTR] = v.x;  d[1 * LSTR] = v.y;
            d[2 * LSTR] = v.z;  d[3 * LSTR] = v.w;
        }
        shinv[tt * 32 + l] = rsqrtf(fmaxf(s, EPS));
    }
    __syncthreads();

    // Grams: 3 warps = 3 grams (aa, bb, ab); lane = output row i.
    // G_ij += sum_l (P[i][l]*w_l) * Q[j][l],  w_l = invP[l]*invQ[l].
    {
        const int g = tid >> 5;   // 0..2
        const int i = tid & 31;
        const float* __restrict__ P  = sh    + ((g == 1) ? CH * LSTR : 0);
        const float* __restrict__ Q  = sh    + ((g == 0) ? 0 : CH * LSTR);
        const float* __restrict__ wP = shinv + ((g == 1) ? 32 : 0);
        const float* __restrict__ wQ = shinv + ((g == 0) ? 0 : 32);
        float* __restrict__ dst = g_gram + (((b * 3 + g) << 10) + (i << 5));

        #pragma unroll
        for (int jg = 0; jg < 4; ++jg) {
            float a0 = 0, a1 = 0, a2 = 0, a3 = 0, a4 = 0, a5 = 0, a6 = 0, a7 = 0;
            #pragma unroll 8
            for (int l = 0; l < 32; ++l) {
                const float p = P[i * LSTR + l] * (wP[l] * wQ[l]);
                const float* q = Q + (jg * 8) * LSTR + l;
                a0 += p * q[0 * LSTR];  a1 += p * q[1 * LSTR];
                a2 += p * q[2 * LSTR];  a3 += p * q[3 * LSTR];
                a4 += p * q[4 * LSTR];  a5 += p * q[5 * LSTR];
                a6 += p * q[6 * LSTR];  a7 += p * q[7 * LSTR];
            }
            atomicAdd(&dst[jg * 8 + 0], a0);  atomicAdd(&dst[jg * 8 + 1], a1);
            atomicAdd(&dst[jg * 8 + 2], a2);  atomicAdd(&dst[jg * 8 + 3], a3);
            atomicAdd(&dst[jg * 8 + 4], a4);  atomicAdd(&dst[jg * 8 + 5], a5);
            atomicAdd(&dst[jg * 8 + 6], a6);  atomicAdd(&dst[jg * 8 + 7], a7);
        }
    }

    // done ticket -> last chunk block finalizes
    __threadfence();
    __syncthreads();
    if (tid == 0)
        s_flag = (atomicAdd(&g_done, 1u) == NCHUNK - 1) ? 1u : 0u;
    __syncthreads();
    if (!s_flag) return;

    __threadfence();   // acquire all gram atomics

    // loss = sum_b ( ||Gaa||^2 + ||Gbb||^2 - 2||Gab||^2 ) / (L^2 * B)
    float local = 0.0f;
    const float4* __restrict__ gv = reinterpret_cast<const float4*>(g_gram);
    #pragma unroll
    for (int k = 0; k < 16; ++k) {                 // 1536 float4 / 96 threads
        const int i4 = tid + k * 96;
        const int g  = (i4 >> 8) % 3;              // 256 float4 per gram
        const float w = (g == 2) ? -2.0f : 1.0f;
        const float4 v = __ldcg(&gv[i4]);
        local += w * (v.x * v.x + v.y * v.y + v.z * v.z + v.w * v.w);
    }
    #pragma unroll
    for (int off = 16; off > 0; off >>= 1)
        local += __shfl_xor_sync(0xFFFFFFFFu, local, off);
    if ((tid & 31) == 0) wsum[tid >> 5] = local;
    __syncthreads();
    if (tid == 0) {
        out[0] = (wsum[0] + wsum[1] + wsum[2]) *
                 (1.0f / ((float)LTOK * (float)LTOK * (float)BATCH));
        g_done = 0u;                                // reset for next replay
    }
    __syncthreads();                                // reads done before zeroing

    // re-zero gram accumulator for next replay
    const float4 z = make_float4(0.f, 0.f, 0.f, 0.f);
    float4* __restrict__ gz = reinterpret_cast<float4*>(g_gram);
    #pragma unroll
    for (int k = 0; k < 16; ++k)
        gz[tid + k * 96] = z;
}

// ---------------------------------------------------------------------------
extern "C" void kernel_launch(void* const* d_in, const int* in_sizes, int n_in,
                              void* d_out, int out_size)
{
    const float* p1 = (const float*)d_in[0];
    const float* p2 = (const float*)d_in[1];
    float* out = (float*)d_out;

    fused_kernel<<<POOL_BLOCKS + NCHUNK, 96>>>(p1, p2, out);
}

// round 15
// speedup vs baseline: 1.3095x; 1.3095x over previous
#include <cuda_runtime.h>
#include <cuda_bf16.h>

// p1, p2: [B=2, C=32, D=96, H=96, W=96] fp32
// pool to S=8 (cells 12^3), L = 512 tokens, C = 32 channels.
// loss = (1/(L^2 B)) * sum_b [ ||Ga||F^2 + ||Gb||F^2 - 2||Gx||F^2 ]
// where G are 32x32 channel Grams of unit-normalized token matrices.
// ||G||^2 decomposes over column strips, so each sim block owns one
// (batch, gram, 8-column strip), computes it over the FULL K=512 from
// g_pooled, and contributes a single scalar atomicAdd. No gram buffer.

#define BATCH 2
#define CH    32
#define DIM   96
#define LTOK  512
#define BLK   12
#define EPS   1e-8f

#define LSTR2 513                 // channel-major row stride (odd -> conflict-free)
#define SIDE  (CH * LSTR2)        // floats per side
#define SIM_BLOCKS 24             // 2 b x 3 g x 4 strips
#define SIM_SMEM (2 * SIDE * (int)sizeof(float))

// pooled tokens token-major: [tensor(2)][b(2)][l(512)][c(32)]
__device__ float g_pooled[2 * BATCH * LTOK * CH];
__device__ float g_acc;
__device__ unsigned int g_done;

// ---------------------------------------------------------------------------
// Kernel 1: pooling — identical math/mapping to the proven 65.3us version.
// One block per (tensor, b, c, pd, ph); 96 threads; 36 affine-offset LDG.128
// per thread with streaming hint. Block 0 resets scalar state for replay.
// ---------------------------------------------------------------------------
__global__ __launch_bounds__(96) void pool_kernel(const float* __restrict__ p1,
                                                  const float* __restrict__ p2)
{
    const int bid = blockIdx.x;
    if (bid == 0 && threadIdx.x == 0) { g_acc = 0.0f; g_done = 0u; }

    const int ph = bid & 7;
    const int pd = (bid >> 3) & 7;
    const int c  = (bid >> 6) & 31;
    const int b  = (bid >> 11) & 1;
    const int t  = bid >> 12;

    const float* __restrict__ in = (t == 0) ? p1 : p2;

    const int tid = threadIdx.x;
    const int f4  = tid % 24;   // w = 4*f4
    const int rs  = tid / 24;   // d chunk [3rs, 3rs+3)

    const float* __restrict__ base =
        in + ((size_t)(b * CH + c)) * (DIM * DIM * DIM)
           + (size_t)(pd * BLK + 3 * rs) * (DIM * DIM)
           + (size_t)ph * BLK * DIM
           + f4 * 4;

    float acc = 0.0f;
    #pragma unroll
    for (int d2 = 0; d2 < 3; ++d2) {
        #pragma unroll
        for (int h = 0; h < 12; ++h) {
            const float4 v = __ldcs(reinterpret_cast<const float4*>(
                base + d2 * (DIM * DIM) + h * DIM));
            acc += (v.x + v.y) + (v.z + v.w);
        }
    }

    __shared__ float sh[96];
    sh[tid] = acc;
    __syncthreads();

    if (tid < 8) {
        float s = 0.0f;
        #pragma unroll
        for (int r2 = 0; r2 < 4; ++r2)
            #pragma unroll
            for (int j = 0; j < 3; ++j)
                s += sh[r2 * 24 + tid * 3 + j];
        const int l = pd * 64 + ph * 8 + tid;
        g_pooled[(((size_t)t * BATCH + b) * LTOK + l) * CH + c] =
            s * (1.0f / (BLK * BLK * BLK));
    }
}

// ---------------------------------------------------------------------------
// Kernel 2: strip Grams. 24 blocks x 256 threads.
//   bid -> b = bid/12, g = (bid/4)%3 (0:aa 1:bb 2:ab), strip = bid%4.
// Load: proven coalesced path — 4 lanes per token, float4 LDG, quad shfl
// norm, normalized STS to channel-major smem (stride 513: writer banks
// 8*sub + r + l all distinct; gram reads i + l all distinct).
// Gram: warp w owns l in [64w, 64w+64); lane = output row i; 8 j-columns
// accumulated in registers (Q reads warp-broadcast). K-split partials
// combined through smem, squared with weight, block-reduced, one scalar
// atomicAdd. Done-counter elects the final writer of out[0].
// ---------------------------------------------------------------------------
extern __shared__ float dyn_sm[];

__global__ __launch_bounds__(256) void sim_kernel(float* __restrict__ out)
{
    float* smP = dyn_sm;
    __shared__ float part[8 * 256];   // [kwarp][i*8+jj]
    __shared__ float wsum[8];
    __shared__ unsigned int s_last;

    const int bidx  = blockIdx.x;
    const int b     = bidx / 12;
    const int g     = (bidx / 4) % 3;
    const int strip = bidx & 3;
    const int tid   = threadIdx.x;

    float* smQ = (g == 2) ? (dyn_sm + SIDE) : smP;
    const int tP = (g == 1) ? 1 : 0;   // tensor for P side (bb uses tensor 1)
    const int nsides = (g == 2) ? 2 : 1;

    // ---- load + normalize side(s): 4 lanes per token --------------------
    const int sub  = tid & 3;          // channels [8*sub, 8*sub+8)
    const int tok4 = tid >> 2;         // 0..63 tokens per pass
    for (int s = 0; s < nsides; ++s) {
        const int t = (s == 0) ? tP : 1;
        float* __restrict__ dstb = (s == 0) ? smP : smQ;
        const float* __restrict__ srcb =
            g_pooled + ((size_t)(t * BATCH + b) * LTOK) * CH;
        #pragma unroll
        for (int pass = 0; pass < 8; ++pass) {
            const int l = pass * 64 + tok4;
            const float* __restrict__ src = srcb + (size_t)l * CH + sub * 8;
            const float4 v0 = __ldcg(reinterpret_cast<const float4*>(src));
            const float4 v1 = __ldcg(reinterpret_cast<const float4*>(src + 4));
            float ssq = v0.x * v0.x + v0.y * v0.y + v0.z * v0.z + v0.w * v0.w
                      + v1.x * v1.x + v1.y * v1.y + v1.z * v1.z + v1.w * v1.w;
            ssq += __shfl_xor_sync(0xFFFFFFFFu, ssq, 1);
            ssq += __shfl_xor_sync(0xFFFFFFFFu, ssq, 2);
            const float r = rsqrtf(fmaxf(ssq, EPS));
            float* __restrict__ d = dstb + (sub * 8) * LSTR2 + l;
            d[0 * LSTR2] = v0.x * r;  d[1 * LSTR2] = v0.y * r;
            d[2 * LSTR2] = v0.z * r;  d[3 * LSTR2] = v0.w * r;
            d[4 * LSTR2] = v1.x * r;  d[5 * LSTR2] = v1.y * r;
            d[6 * LSTR2] = v1.z * r;  d[7 * LSTR2] = v1.w * r;
        }
    }
    __syncthreads();

    // ---- strip gram, K split across 8 warps ------------------------------
    const int w = tid >> 5;            // warp: l-range [64w, 64w+64)
    const int i = tid & 31;            // output row (channel)
    const int j0 = strip * 8;

    float a0 = 0, a1 = 0, a2 = 0, a3 = 0, a4 = 0, a5 = 0, a6 = 0, a7 = 0;
    const float* __restrict__ Pr = smP + (size_t)i * LSTR2 + w * 64;
    const float* __restrict__ Qb = smQ + (size_t)j0 * LSTR2 + w * 64;
    #pragma unroll 4
    for (int lo = 0; lo < 64; ++lo) {
        const float p = Pr[lo];
        a0 += p * Qb[0 * LSTR2 + lo];  a1 += p * Qb[1 * LSTR2 + lo];
        a2 += p * Qb[2 * LSTR2 + lo];  a3 += p * Qb[3 * LSTR2 + lo];
        a4 += p * Qb[4 * LSTR2 + lo];  a5 += p * Qb[5 * LSTR2 + lo];
        a6 += p * Qb[6 * LSTR2 + lo];  a7 += p * Qb[7 * LSTR2 + lo];
    }
    float* __restrict__ pr = part + w * 256 + i * 8;
    pr[0] = a0;  pr[1] = a1;  pr[2] = a2;  pr[3] = a3;
    pr[4] = a4;  pr[5] = a5;  pr[6] = a6;  pr[7] = a7;
    __syncthreads();

    // ---- combine K-splits, square with weight, block reduce --------------
    float v = 0.0f;
    #pragma unroll
    for (int w2 = 0; w2 < 8; ++w2)
        v += part[w2 * 256 + tid];
    const float wgt = (g == 2) ? -2.0f : 1.0f;
    float local = wgt * v * v;

    #pragma unroll
    for (int off = 16; off > 0; off >>= 1)
        local += __shfl_xor_sync(0xFFFFFFFFu, local, off);
    if ((tid & 31) == 0) wsum[tid >> 5] = local;
    __syncthreads();

    if (tid == 0) {
        float s = 0.0f;
        #pragma unroll
        for (int k = 0; k < 8; ++k) s += wsum[k];
        atomicAdd(&g_acc, s);
        __threadfence();
        s_last = (atomicAdd(&g_done, 1u) == SIM_BLOCKS - 1) ? 1u : 0u;
        if (s_last) {
            __threadfence();
            const float total = *((volatile float*)&g_acc);
            out[0] = total * (1.0f / ((float)LTOK * (float)LTOK * (float)BATCH));
        }
    }
}

// ---------------------------------------------------------------------------
extern "C" void kernel_launch(void* const* d_in, const int* in_sizes, int n_in,
                              void* d_out, int out_size)
{
    const float* p1 = (const float*)d_in[0];
    const float* p2 = (const float*)d_in[1];
    float* out = (float*)d_out;

    cudaFuncSetAttribute(sim_kernel, cudaFuncAttributeMaxDynamicSharedMemorySize,
                         SIM_SMEM);

    pool_kernel<<<8192, 96>>>(p1, p2);               // 2*2*32*8*8 blocks
    sim_kernel<<<SIM_BLOCKS, 256, SIM_SMEM>>>(out);
}